// round 12
// baseline (speedup 1.0000x reference)
#include <cuda_runtime.h>
#include <cuda_bf16.h>

#define NN 64
#define SS 512
#define DD 512
#define CC 1024
#define GRID 128
#define NTHREADS 256

// ---------------- device scratch (static, no allocations) ----------------
__device__ float g_X[(size_t)NN * SS * DD];   // LN'd masked inputs (64 MB)
__device__ float g_ht[NN * DD];
__device__ float g_gs[NN * DD];
__device__ float g_inter[NN * CC];
__device__ float g_cont[NN * 4 * DD];
__device__ unsigned g_cnt;
__device__ unsigned g_sense;

typedef unsigned long long ull;

__device__ __forceinline__ void fma2(ull& d, ull a, ull b) {
    asm("fma.rn.f32x2 %0, %1, %2, %0;" : "+l"(d) : "l"(a), "l"(b));
}
__device__ __forceinline__ ull dup2(float f) {
    ull r; asm("mov.b64 %0, {%1, %1};" : "=l"(r) : "f"(f)); return r;
}
__device__ __forceinline__ float2 unp(ull v) {
    float2 r; asm("mov.b64 {%0, %1}, %2;" : "=f"(r.x), "=f"(r.y) : "l"(v)); return r;
}
__device__ __forceinline__ float sigm(float x) { return 1.f / (1.f + expf(-x)); }
__device__ __forceinline__ float gelu_t(float x) {
    float u = x + 0.044715f * x * x * x;
    return 0.5f * x * (1.f + tanhf(0.7978845608028654f * u));
}
__device__ __forceinline__ float4 ldcg4(const float* p) {
    return __ldcg((const float4*)p);
}

// =================== kernel 1: g_X = (seq*mask) @ W_init + b_init ===================
__global__ void __launch_bounds__(256) k_init_gemm(
    const float* __restrict__ seq, const float* __restrict__ mask,
    const float* __restrict__ Wi, const float* __restrict__ bi)
{
    __shared__ float As[16][64];
    __shared__ float Bs[16][64];
    const int tid = threadIdx.x;
    const int row0 = blockIdx.y * 64;     // rows = n*S + s
    const int n0 = blockIdx.x * 64;
    const int lm = tid >> 2;              // row for A-load (0..63)
    const int kq = (tid & 3) * 4;         // k-quad for A-load
    const int bk = tid >> 4;              // k for B-load (0..15)
    const int bn = (tid & 15) * 4;        // n-quad for B-load
    const int ty = tid >> 4;              // m-group for compute
    const int tx = tid & 15;              // n-group for compute
    const float mval = mask[row0 + lm];

    float acc[4][4];
#pragma unroll
    for (int i = 0; i < 4; i++)
#pragma unroll
        for (int j = 0; j < 4; j++) acc[i][j] = 0.f;

    for (int kt = 0; kt < DD / 16; kt++) {
        float4 a = *(const float4*)&seq[(size_t)(row0 + lm) * DD + kt * 16 + kq];
        As[kq + 0][lm] = a.x * mval;
        As[kq + 1][lm] = a.y * mval;
        As[kq + 2][lm] = a.z * mval;
        As[kq + 3][lm] = a.w * mval;
        *(float4*)&Bs[bk][bn] = *(const float4*)&Wi[(size_t)(kt * 16 + bk) * DD + n0 + bn];
        __syncthreads();
#pragma unroll
        for (int k = 0; k < 16; k++) {
            float4 av = *(const float4*)&As[k][ty * 4];
            float4 bv = *(const float4*)&Bs[k][tx * 4];
            float am[4] = {av.x, av.y, av.z, av.w};
            float bb[4] = {bv.x, bv.y, bv.z, bv.w};
#pragma unroll
            for (int i = 0; i < 4; i++)
#pragma unroll
                for (int j = 0; j < 4; j++) acc[i][j] += am[i] * bb[j];
        }
        __syncthreads();
    }
#pragma unroll
    for (int i = 0; i < 4; i++)
#pragma unroll
        for (int j = 0; j < 4; j++) {
            int n = n0 + tx * 4 + j;
            g_X[(size_t)(row0 + ty * 4 + i) * DD + n] = acc[i][j] + bi[n];
        }
}

// ============ kernel 2: in-place LN rows of g_X, * mask; reset barrier ============
__global__ void __launch_bounds__(128) k_ln(
    const float* __restrict__ lng, const float* __restrict__ lnb,
    const float* __restrict__ mask)
{
    if (blockIdx.x == 0 && threadIdx.x == 0) { g_cnt = 0; g_sense = 0; }
    const int row = blockIdx.x;           // n*S + s
    const int tid = threadIdx.x;
    float* xp = g_X + (size_t)row * DD;
    float4 v = *(float4*)(xp + tid * 4);
    __shared__ float sc[16];

    float s = v.x + v.y + v.z + v.w;
#pragma unroll
    for (int o = 16; o; o >>= 1) s += __shfl_xor_sync(0xffffffffu, s, o);
    if ((tid & 31) == 0) sc[tid >> 5] = s;
    __syncthreads();
    if (tid == 0) sc[8] = (sc[0] + sc[1] + sc[2] + sc[3]) * (1.f / DD);
    __syncthreads();
    float m = sc[8];

    float a0 = v.x - m, a1 = v.y - m, a2 = v.z - m, a3 = v.w - m;
    float q = a0 * a0 + a1 * a1 + a2 * a2 + a3 * a3;
#pragma unroll
    for (int o = 16; o; o >>= 1) q += __shfl_xor_sync(0xffffffffu, q, o);
    if ((tid & 31) == 0) sc[tid >> 5] = q;
    __syncthreads();
    if (tid == 0) sc[9] = rsqrtf((sc[0] + sc[1] + sc[2] + sc[3]) * (1.f / DD) + 1e-5f);
    __syncthreads();
    float rs = sc[9];

    float mval = mask[row];
    float4 g4 = *(const float4*)(lng + tid * 4);
    float4 b4 = *(const float4*)(lnb + tid * 4);
    v.x = (a0 * rs * g4.x + b4.x) * mval;
    v.y = (a1 * rs * g4.y + b4.y) * mval;
    v.z = (a2 * rs * g4.z + b4.z) * mval;
    v.w = (a3 * rs * g4.w + b4.w) * mval;
    *(float4*)(xp + tid * 4) = v;
}

// =================== persistent recurrence kernel ===================
// Fence-free global barrier: release-atomic arrive, acquire-load spin.
// No membar.gl is ever executed, so L1D is never flushed (CCTL.IVALL is only
// emitted for fence scope >= cluster). All cross-block data moves with
// .cg stores/loads (L2), so no stale-L1 hazard exists.
__device__ __forceinline__ void gbar(unsigned* barc) {
    __syncthreads();
    unsigned target = ++(*barc);
    if (threadIdx.x == 0) {
        unsigned prev;
        asm volatile("atom.release.gpu.add.u32 %0, [%1], 1;"
                     : "=r"(prev) : "l"(&g_cnt) : "memory");
        if (prev == GRID - 1) {
            asm volatile("st.relaxed.gpu.u32 [%0], %1;"
                         :: "l"(&g_cnt), "r"(0u) : "memory");
            asm volatile("st.release.gpu.u32 [%0], %1;"
                         :: "l"(&g_sense), "r"(target) : "memory");
        } else {
            unsigned s;
            do {
                asm volatile("ld.acquire.gpu.u32 %0, [%1];"
                             : "=r"(s) : "l"(&g_sense) : "memory");
            } while (s < target);
        }
    }
    __syncthreads();
}

// block sum over 256 threads (8 warps)
__device__ __forceinline__ float bsum(float v, float* sc) {
    int lane = threadIdx.x & 31, w = threadIdx.x >> 5;
#pragma unroll
    for (int o = 16; o; o >>= 1) v += __shfl_xor_sync(0xffffffffu, v, o);
    if (lane == 0) sc[w] = v;
    __syncthreads();
    if (w == 0) {
        float s = (lane < 8) ? sc[lane] : 0.f;
#pragma unroll
        for (int o = 4; o; o >>= 1) s += __shfl_xor_sync(0xffffffffu, s, o);
        if (lane == 0) sc[8] = s;
    }
    __syncthreads();
    float r = sc[8];
    __syncthreads();
    return r;
}

__global__ void __launch_bounds__(NTHREADS, 1) k_recur(
    const float* __restrict__ mask, const float* __restrict__ START,
    const float* __restrict__ W1, const float* __restrict__ b1,
    const float* __restrict__ W2, const float* __restrict__ b2,
    const float* __restrict__ lng, const float* __restrict__ lnb,
    float* __restrict__ out)
{
    // per-warp staging: 8 kk x 64 m duplicated f32x2 (4 KB/warp, 32 KB total)
    // after each warp's k-loop, its slot is reused for its fp32 partials.
    __shared__ ull A2[8][512];
    __shared__ float scC[16];

    const int tid = threadIdx.x;
    const int lane = tid & 31;
    const int warp = tid >> 5;
    const int b = blockIdx.x;
    const int mg = lane & 15;
    const int ng = lane >> 4;
    const int m0 = mg * 4;
    const int k0 = warp * 128;
    ull* const Aw = &A2[warp][0];
    float* const Rw = (float*)Aw;          // this warp's 1024-float partial slot
    float* const Rall = (float*)A2;
    unsigned barc = 0;

    // init carry
    if (b < NN) {
#pragma unroll
        for (int j = 0; j < 2; j++) {
            int d = tid + 256 * j;
            float s = START[d];
            g_ht[b * DD + d] = s;
            g_gs[b * DD + d] = s;
        }
    }
    gbar(&barc);

    const int nA0 = b * 8;
    const int nB0 = b * 16;

    for (int t = 0; t < SS; t++) {
        // ---------- phase A: inter = gelu(cat @ W1 + b1); block owns 8 cols ----------
        {
            ull acc[4][2];
#pragma unroll
            for (int i = 0; i < 4; i++) { acc[i][0] = 0; acc[i][1] = 0; }

            const float *base0, *base1;
            if (warp < 4) {
                base0 = g_ht + (size_t)lane * DD + k0;
                base1 = g_ht + (size_t)(lane + 32) * DD + k0;
            } else {
                size_t off = (size_t)t * DD + (k0 - 512);
                base0 = g_X + (size_t)lane * SS * DD + off;
                base1 = g_X + (size_t)(lane + 32) * SS * DD + off;
            }
            // software pipeline: prefetch next kc while computing current
            float4 c0 = ldcg4(base0), c1 = ldcg4(base0 + 4);
            float4 c2 = ldcg4(base1), c3 = ldcg4(base1 + 4);

            for (int kc = 0; kc < 16; kc++) {
                float4 p0, p1, p2, p3;
                if (kc < 15) {
                    const float* q0 = base0 + (kc + 1) * 8;
                    const float* q1 = base1 + (kc + 1) * 8;
                    p0 = ldcg4(q0); p1 = ldcg4(q0 + 4);
                    p2 = ldcg4(q1); p3 = ldcg4(q1 + 4);
                } else {
                    p0 = c0; p1 = c1; p2 = c2; p3 = c3;
                }
                __syncwarp();
                const int m2 = lane + 32;
                Aw[0 * 64 + lane] = dup2(c0.x); Aw[1 * 64 + lane] = dup2(c0.y);
                Aw[2 * 64 + lane] = dup2(c0.z); Aw[3 * 64 + lane] = dup2(c0.w);
                Aw[4 * 64 + lane] = dup2(c1.x); Aw[5 * 64 + lane] = dup2(c1.y);
                Aw[6 * 64 + lane] = dup2(c1.z); Aw[7 * 64 + lane] = dup2(c1.w);
                Aw[0 * 64 + m2] = dup2(c2.x);   Aw[1 * 64 + m2] = dup2(c2.y);
                Aw[2 * 64 + m2] = dup2(c2.z);   Aw[3 * 64 + m2] = dup2(c2.w);
                Aw[4 * 64 + m2] = dup2(c3.x);   Aw[5 * 64 + m2] = dup2(c3.y);
                Aw[6 * 64 + m2] = dup2(c3.z);   Aw[7 * 64 + m2] = dup2(c3.w);
                __syncwarp();
                const float* wrow = W1 + (size_t)(k0 + kc * 8) * CC + nA0 + ng * 4;
#pragma unroll
                for (int kk = 0; kk < 8; kk++) {
                    ulonglong2 pa = *(const ulonglong2*)(Aw + kk * 64 + m0);
                    ulonglong2 pb = *(const ulonglong2*)(Aw + kk * 64 + m0 + 2);
                    ulonglong2 w  = *(const ulonglong2*)(wrow + (size_t)kk * CC);
                    fma2(acc[0][0], pa.x, w.x); fma2(acc[0][1], pa.x, w.y);
                    fma2(acc[1][0], pa.y, w.x); fma2(acc[1][1], pa.y, w.y);
                    fma2(acc[2][0], pb.x, w.x); fma2(acc[2][1], pb.x, w.y);
                    fma2(acc[3][0], pb.y, w.x); fma2(acc[3][1], pb.y, w.y);
                }
                c0 = p0; c1 = p1; c2 = p2; c3 = p3;
            }
            __syncwarp();   // all lanes done reading Aw before partials overwrite it
#pragma unroll
            for (int mi = 0; mi < 4; mi++)
#pragma unroll
                for (int p = 0; p < 2; p++) {
                    float2 f = unp(acc[mi][p]);
                    int idx = (m0 + mi) * 8 + ng * 4 + p * 2;
                    Rw[idx] = f.x; Rw[idx + 1] = f.y;
                }
            __syncthreads();
#pragma unroll
            for (int j = 0; j < 2; j++) {
                int idx = tid + 256 * j;
                int m = idx >> 3, nl = idx & 7;
                float s = b1[nA0 + nl];
#pragma unroll
                for (int w = 0; w < 8; w++) s += Rall[w * 1024 + idx];
                __stcg(&g_inter[m * CC + nA0 + nl], gelu_t(s));
            }
        }
        gbar(&barc);

        // ---------- phase B: cont = inter @ W2 + b2; block owns 16 cols ----------
        {
            ull acc[4][4];
#pragma unroll
            for (int i = 0; i < 4; i++)
#pragma unroll
                for (int j = 0; j < 4; j++) acc[i][j] = 0;

            const float* base0 = g_inter + (size_t)lane * CC + k0;
            const float* base1 = g_inter + (size_t)(lane + 32) * CC + k0;
            float4 c0 = ldcg4(base0), c1 = ldcg4(base0 + 4);
            float4 c2 = ldcg4(base1), c3 = ldcg4(base1 + 4);

            for (int kc = 0; kc < 16; kc++) {
                float4 p0, p1, p2, p3;
                if (kc < 15) {
                    const float* q0 = base0 + (kc + 1) * 8;
                    const float* q1 = base1 + (kc + 1) * 8;
                    p0 = ldcg4(q0); p1 = ldcg4(q0 + 4);
                    p2 = ldcg4(q1); p3 = ldcg4(q1 + 4);
                } else {
                    p0 = c0; p1 = c1; p2 = c2; p3 = c3;
                }
                __syncwarp();
                const int m2 = lane + 32;
                Aw[0 * 64 + lane] = dup2(c0.x); Aw[1 * 64 + lane] = dup2(c0.y);
                Aw[2 * 64 + lane] = dup2(c0.z); Aw[3 * 64 + lane] = dup2(c0.w);
                Aw[4 * 64 + lane] = dup2(c1.x); Aw[5 * 64 + lane] = dup2(c1.y);
                Aw[6 * 64 + lane] = dup2(c1.z); Aw[7 * 64 + lane] = dup2(c1.w);
                Aw[0 * 64 + m2] = dup2(c2.x);   Aw[1 * 64 + m2] = dup2(c2.y);
                Aw[2 * 64 + m2] = dup2(c2.z);   Aw[3 * 64 + m2] = dup2(c2.w);
                Aw[4 * 64 + m2] = dup2(c3.x);   Aw[5 * 64 + m2] = dup2(c3.y);
                Aw[6 * 64 + m2] = dup2(c3.z);   Aw[7 * 64 + m2] = dup2(c3.w);
                __syncwarp();
                const float* wrow = W2 + (size_t)(k0 + kc * 8) * (4 * DD) + nB0 + ng * 8;
#pragma unroll
                for (int kk = 0; kk < 8; kk++) {
                    ulonglong2 pa = *(const ulonglong2*)(Aw + kk * 64 + m0);
                    ulonglong2 pb = *(const ulonglong2*)(Aw + kk * 64 + m0 + 2);
                    const float* wr = wrow + (size_t)kk * (4 * DD);
                    ulonglong2 w0 = *(const ulonglong2*)(wr);
                    ulonglong2 w1 = *(const ulonglong2*)(wr + 4);
                    ull av[4] = {pa.x, pa.y, pb.x, pb.y};
#pragma unroll
                    for (int mi = 0; mi < 4; mi++) {
                        fma2(acc[mi][0], av[mi], w0.x);
                        fma2(acc[mi][1], av[mi], w0.y);
                        fma2(acc[mi][2], av[mi], w1.x);
                        fma2(acc[mi][3], av[mi], w1.y);
                    }
                }
                c0 = p0; c1 = p1; c2 = p2; c3 = p3;
            }
            __syncwarp();
#pragma unroll
            for (int mi = 0; mi < 4; mi++)
#pragma unroll
                for (int np = 0; np < 4; np++) {
                    float2 f = unp(acc[mi][np]);
                    int idx = (m0 + mi) * 16 + ng * 8 + np * 2;
                    Rw[idx] = f.x; Rw[idx + 1] = f.y;
                }
            __syncthreads();
#pragma unroll
            for (int j = 0; j < 4; j++) {
                int idx = tid + 256 * j;
                int m = idx >> 4, nl = idx & 15;
                float s = b2[nB0 + nl];
#pragma unroll
                for (int w = 0; w < 8; w++) s += Rall[w * 1024 + idx];
                __stcg(&g_cont[m * (4 * DD) + nB0 + nl], s);
            }
        }
        gbar(&barc);

        // ---------- phase C: gates + LN + state update (blocks 0..63) ----------
        if (b < NN) {
            float mval = mask[(size_t)b * SS + t];
            float vv[2];
#pragma unroll
            for (int h = 0; h < 2; h++) {
                int d = tid + 256 * h;
                const float* cb = g_cont + b * (4 * DD);
                float c0 = __ldcg(cb + d);
                float c1 = __ldcg(cb + 512 + d);
                float c2 = __ldcg(cb + 1024 + d);
                float c3 = __ldcg(cb + 1536 + d);
                float h0 = g_ht[b * DD + d];
                float x0 = g_X[((size_t)b * SS + t) * DD + d];
                vv[h] = sigm(c0) * h0 + sigm(c1) * x0 + sigm(c2) * c3;
            }
            float mean = bsum(vv[0] + vv[1], scC) * (1.f / DD);
            float e0 = vv[0] - mean, e1 = vv[1] - mean;
            float var = bsum(e0 * e0 + e1 * e1, scC) * (1.f / DD);
            float rs = rsqrtf(var + 1e-5f);
#pragma unroll
            for (int h = 0; h < 2; h++) {
                int d = tid + 256 * h;
                float hn = (vv[h] - mean) * rs * lng[d] + lnb[d];
                g_ht[b * DD + d] = hn;
                out[((size_t)b * SS + t) * DD + d] = hn * mval;
                g_gs[b * DD + d] = mval * hn + (1.f - mval) * g_gs[b * DD + d];
            }
        }
        gbar(&barc);
    }

    // final global_state
    if (b < NN) {
#pragma unroll
        for (int h = 0; h < 2; h++) {
            int d = tid + 256 * h;
            out[(size_t)NN * SS * DD + b * DD + d] = g_gs[b * DD + d];
        }
    }
}

extern "C" void kernel_launch(void* const* d_in, const int* in_sizes, int n_in,
                              void* d_out, int out_size) {
    (void)in_sizes; (void)n_in; (void)out_size;
    const float* seq   = (const float*)d_in[0];
    const float* mask  = (const float*)d_in[1];
    const float* START = (const float*)d_in[2];
    const float* Wi    = (const float*)d_in[3];
    const float* bi    = (const float*)d_in[4];
    const float* W1    = (const float*)d_in[5];
    const float* b1    = (const float*)d_in[6];
    const float* W2    = (const float*)d_in[7];
    const float* b2    = (const float*)d_in[8];
    const float* lng   = (const float*)d_in[9];
    const float* lnb   = (const float*)d_in[10];
    float* out = (float*)d_out;

    dim3 g1(DD / 64, (NN * SS) / 64);
    k_init_gemm<<<g1, 256>>>(seq, mask, Wi, bi);
    k_ln<<<NN * SS, 128>>>(lng, lnb, mask);
    k_recur<<<GRID, NTHREADS>>>(mask, START, W1, b1, W2, b2, lng, lnb, out);
}

// round 13
// speedup vs baseline: 1.7575x; 1.7575x over previous
#include <cuda_runtime.h>
#include <cuda_bf16.h>

#define NN 64
#define SS 512
#define DD 512
#define CC 1024
#define GRID 128
#define NTHREADS 256

// dynamic smem layout for k_recur (bytes):
//   [0,      32768)  A2 staging: 8 warps x 512 ull
//   [32768,  65536)  sW1: 1024 rows x 8 floats   (block's W1 column slice)
//   [65536, 131072)  sW2: 1024 rows x 16 floats  (block's W2 column slice)
#define SMEM_RECUR (32768 + 32768 + 65536)

// ---------------- device scratch (static, no allocations) ----------------
__device__ float g_X[(size_t)NN * SS * DD];   // LN'd masked inputs (64 MB)
__device__ float g_ht[NN * DD];
__device__ float g_gs[NN * DD];
__device__ float g_inter[NN * CC];
__device__ float g_cont[NN * 4 * DD];
__device__ unsigned g_cnt;
__device__ unsigned g_sense;

typedef unsigned long long ull;

__device__ __forceinline__ void fma2(ull& d, ull a, ull b) {
    asm("fma.rn.f32x2 %0, %1, %2, %0;" : "+l"(d) : "l"(a), "l"(b));
}
__device__ __forceinline__ ull dup2(float f) {
    ull r; asm("mov.b64 %0, {%1, %1};" : "=l"(r) : "f"(f)); return r;
}
__device__ __forceinline__ float2 unp(ull v) {
    float2 r; asm("mov.b64 {%0, %1}, %2;" : "=f"(r.x), "=f"(r.y) : "l"(v)); return r;
}
__device__ __forceinline__ float sigm(float x) { return 1.f / (1.f + expf(-x)); }
__device__ __forceinline__ float gelu_t(float x) {
    float u = x + 0.044715f * x * x * x;
    return 0.5f * x * (1.f + tanhf(0.7978845608028654f * u));
}
__device__ __forceinline__ float4 ldcg4(const float* p) {
    return __ldcg((const float4*)p);
}

// =================== kernel 1: g_X = (seq*mask) @ W_init + b_init ===================
__global__ void __launch_bounds__(256) k_init_gemm(
    const float* __restrict__ seq, const float* __restrict__ mask,
    const float* __restrict__ Wi, const float* __restrict__ bi)
{
    __shared__ float As[16][64];
    __shared__ float Bs[16][64];
    const int tid = threadIdx.x;
    const int row0 = blockIdx.y * 64;     // rows = n*S + s
    const int n0 = blockIdx.x * 64;
    const int lm = tid >> 2;              // row for A-load (0..63)
    const int kq = (tid & 3) * 4;         // k-quad for A-load
    const int bk = tid >> 4;              // k for B-load (0..15)
    const int bn = (tid & 15) * 4;        // n-quad for B-load
    const int ty = tid >> 4;              // m-group for compute
    const int tx = tid & 15;              // n-group for compute
    const float mval = mask[row0 + lm];

    float acc[4][4];
#pragma unroll
    for (int i = 0; i < 4; i++)
#pragma unroll
        for (int j = 0; j < 4; j++) acc[i][j] = 0.f;

    for (int kt = 0; kt < DD / 16; kt++) {
        float4 a = *(const float4*)&seq[(size_t)(row0 + lm) * DD + kt * 16 + kq];
        As[kq + 0][lm] = a.x * mval;
        As[kq + 1][lm] = a.y * mval;
        As[kq + 2][lm] = a.z * mval;
        As[kq + 3][lm] = a.w * mval;
        *(float4*)&Bs[bk][bn] = *(const float4*)&Wi[(size_t)(kt * 16 + bk) * DD + n0 + bn];
        __syncthreads();
#pragma unroll
        for (int k = 0; k < 16; k++) {
            float4 av = *(const float4*)&As[k][ty * 4];
            float4 bv = *(const float4*)&Bs[k][tx * 4];
            float am[4] = {av.x, av.y, av.z, av.w};
            float bb[4] = {bv.x, bv.y, bv.z, bv.w};
#pragma unroll
            for (int i = 0; i < 4; i++)
#pragma unroll
                for (int j = 0; j < 4; j++) acc[i][j] += am[i] * bb[j];
        }
        __syncthreads();
    }
#pragma unroll
    for (int i = 0; i < 4; i++)
#pragma unroll
        for (int j = 0; j < 4; j++) {
            int n = n0 + tx * 4 + j;
            g_X[(size_t)(row0 + ty * 4 + i) * DD + n] = acc[i][j] + bi[n];
        }
}

// ============ kernel 2: in-place LN rows of g_X, * mask; reset barrier ============
__global__ void __launch_bounds__(128) k_ln(
    const float* __restrict__ lng, const float* __restrict__ lnb,
    const float* __restrict__ mask)
{
    if (blockIdx.x == 0 && threadIdx.x == 0) { g_cnt = 0; g_sense = 0; }
    const int row = blockIdx.x;           // n*S + s
    const int tid = threadIdx.x;
    float* xp = g_X + (size_t)row * DD;
    float4 v = *(float4*)(xp + tid * 4);
    __shared__ float sc[16];

    float s = v.x + v.y + v.z + v.w;
#pragma unroll
    for (int o = 16; o; o >>= 1) s += __shfl_xor_sync(0xffffffffu, s, o);
    if ((tid & 31) == 0) sc[tid >> 5] = s;
    __syncthreads();
    if (tid == 0) sc[8] = (sc[0] + sc[1] + sc[2] + sc[3]) * (1.f / DD);
    __syncthreads();
    float m = sc[8];

    float a0 = v.x - m, a1 = v.y - m, a2 = v.z - m, a3 = v.w - m;
    float q = a0 * a0 + a1 * a1 + a2 * a2 + a3 * a3;
#pragma unroll
    for (int o = 16; o; o >>= 1) q += __shfl_xor_sync(0xffffffffu, q, o);
    if ((tid & 31) == 0) sc[tid >> 5] = q;
    __syncthreads();
    if (tid == 0) sc[9] = rsqrtf((sc[0] + sc[1] + sc[2] + sc[3]) * (1.f / DD) + 1e-5f);
    __syncthreads();
    float rs = sc[9];

    float mval = mask[row];
    float4 g4 = *(const float4*)(lng + tid * 4);
    float4 b4 = *(const float4*)(lnb + tid * 4);
    v.x = (a0 * rs * g4.x + b4.x) * mval;
    v.y = (a1 * rs * g4.y + b4.y) * mval;
    v.z = (a2 * rs * g4.z + b4.z) * mval;
    v.w = (a3 * rs * g4.w + b4.w) * mval;
    *(float4*)(xp + tid * 4) = v;
}

// =================== persistent recurrence kernel ===================
// Fence-free global barrier: release-atomic arrive, relaxed-poll + single
// acquire-load on success. No membar.gl anywhere => L1D is never flushed.
// All cross-block data moves with .cg stores/loads (L2).
__device__ __forceinline__ void gbar(unsigned* barc) {
    __syncthreads();
    unsigned target = ++(*barc);
    if (threadIdx.x == 0) {
        unsigned prev;
        asm volatile("atom.release.gpu.add.u32 %0, [%1], 1;"
                     : "=r"(prev) : "l"(&g_cnt) : "memory");
        if (prev == GRID - 1) {
            asm volatile("st.relaxed.gpu.u32 [%0], %1;"
                         :: "l"(&g_cnt), "r"(0u) : "memory");
            asm volatile("st.release.gpu.u32 [%0], %1;"
                         :: "l"(&g_sense), "r"(target) : "memory");
        } else {
            unsigned s;
            do {
                asm volatile("ld.relaxed.gpu.u32 %0, [%1];"
                             : "=r"(s) : "l"(&g_sense) : "memory");
            } while (s < target);
            asm volatile("ld.acquire.gpu.u32 %0, [%1];"
                         : "=r"(s) : "l"(&g_sense) : "memory");
        }
    }
    __syncthreads();
}

// block sum over 256 threads (8 warps)
__device__ __forceinline__ float bsum(float v, float* sc) {
    int lane = threadIdx.x & 31, w = threadIdx.x >> 5;
#pragma unroll
    for (int o = 16; o; o >>= 1) v += __shfl_xor_sync(0xffffffffu, v, o);
    if (lane == 0) sc[w] = v;
    __syncthreads();
    if (w == 0) {
        float s = (lane < 8) ? sc[lane] : 0.f;
#pragma unroll
        for (int o = 4; o; o >>= 1) s += __shfl_xor_sync(0xffffffffu, s, o);
        if (lane == 0) sc[8] = s;
    }
    __syncthreads();
    float r = sc[8];
    __syncthreads();
    return r;
}

__global__ void __launch_bounds__(NTHREADS, 1) k_recur(
    const float* __restrict__ mask, const float* __restrict__ START,
    const float* __restrict__ W1, const float* __restrict__ b1,
    const float* __restrict__ W2, const float* __restrict__ b2,
    const float* __restrict__ lng, const float* __restrict__ lnb,
    float* __restrict__ out)
{
    extern __shared__ char smch[];
    ull* const A2 = (ull*)smch;                         // 8 x 512 ull (32 KB)
    float* const sW1 = (float*)(smch + 32768);          // [1024][8]  (32 KB)
    float* const sW2 = (float*)(smch + 65536);          // [1024][16] (64 KB)
    __shared__ float scC[16];

    const int tid = threadIdx.x;
    const int lane = tid & 31;
    const int warp = tid >> 5;
    const int b = blockIdx.x;
    const int mg = lane & 15;
    const int ng = lane >> 4;
    const int m0 = mg * 4;
    const int k0 = warp * 128;
    ull* const Aw = A2 + warp * 512;
    float* const Rw = (float*)Aw;          // this warp's 1024-float partial slot
    float* const Rall = (float*)A2;
    unsigned barc = 0;

    const int nA0 = b * 8;
    const int nB0 = b * 16;

    // ---- one-time: copy this block's weight slices into smem ----
    // sW1[k][0..8) = W1[k][nA0 .. nA0+8)
    for (int i = tid; i < CC * 2; i += NTHREADS) {      // 2048 float4
        int row = i >> 1, half = i & 1;
        *(float4*)(sW1 + (size_t)row * 8 + half * 4) =
            *(const float4*)(W1 + (size_t)row * CC + nA0 + half * 4);
    }
    // sW2[k][0..16) = W2[k][nB0 .. nB0+16)
    for (int i = tid; i < CC * 4; i += NTHREADS) {      // 4096 float4
        int row = i >> 2, q = i & 3;
        *(float4*)(sW2 + (size_t)row * 16 + q * 4) =
            *(const float4*)(W2 + (size_t)row * (4 * DD) + nB0 + q * 4);
    }

    // init carry
    if (b < NN) {
#pragma unroll
        for (int j = 0; j < 2; j++) {
            int d = tid + 256 * j;
            float s = START[d];
            g_ht[b * DD + d] = s;
            g_gs[b * DD + d] = s;
        }
    }
    gbar(&barc);   // also orders smem weight fill before use (syncthreads inside)

    for (int t = 0; t < SS; t++) {
        // ---------- phase A: inter = gelu(cat @ W1 + b1); block owns 8 cols ----------
        {
            ull acc[4][2];
#pragma unroll
            for (int i = 0; i < 4; i++) { acc[i][0] = 0; acc[i][1] = 0; }

            const float *base0, *base1;
            if (warp < 4) {
                base0 = g_ht + (size_t)lane * DD + k0;
                base1 = g_ht + (size_t)(lane + 32) * DD + k0;
            } else {
                size_t off = (size_t)t * DD + (k0 - 512);
                base0 = g_X + (size_t)lane * SS * DD + off;
                base1 = g_X + (size_t)(lane + 32) * SS * DD + off;
            }
            // software pipeline: prefetch next kc while computing current
            float4 c0 = ldcg4(base0), c1 = ldcg4(base0 + 4);
            float4 c2 = ldcg4(base1), c3 = ldcg4(base1 + 4);

            const float* wA = sW1 + (size_t)k0 * 8 + ng * 4;

            for (int kc = 0; kc < 16; kc++) {
                float4 p0, p1, p2, p3;
                if (kc < 15) {
                    const float* q0 = base0 + (kc + 1) * 8;
                    const float* q1 = base1 + (kc + 1) * 8;
                    p0 = ldcg4(q0); p1 = ldcg4(q0 + 4);
                    p2 = ldcg4(q1); p3 = ldcg4(q1 + 4);
                } else {
                    p0 = c0; p1 = c1; p2 = c2; p3 = c3;
                }
                __syncwarp();
                const int m2 = lane + 32;
                Aw[0 * 64 + lane] = dup2(c0.x); Aw[1 * 64 + lane] = dup2(c0.y);
                Aw[2 * 64 + lane] = dup2(c0.z); Aw[3 * 64 + lane] = dup2(c0.w);
                Aw[4 * 64 + lane] = dup2(c1.x); Aw[5 * 64 + lane] = dup2(c1.y);
                Aw[6 * 64 + lane] = dup2(c1.z); Aw[7 * 64 + lane] = dup2(c1.w);
                Aw[0 * 64 + m2] = dup2(c2.x);   Aw[1 * 64 + m2] = dup2(c2.y);
                Aw[2 * 64 + m2] = dup2(c2.z);   Aw[3 * 64 + m2] = dup2(c2.w);
                Aw[4 * 64 + m2] = dup2(c3.x);   Aw[5 * 64 + m2] = dup2(c3.y);
                Aw[6 * 64 + m2] = dup2(c3.z);   Aw[7 * 64 + m2] = dup2(c3.w);
                __syncwarp();
                const float* wrow = wA + (size_t)kc * 64;   // 8 k-rows x 8 floats
#pragma unroll
                for (int kk = 0; kk < 8; kk++) {
                    ulonglong2 pa = *(const ulonglong2*)(Aw + kk * 64 + m0);
                    ulonglong2 pb = *(const ulonglong2*)(Aw + kk * 64 + m0 + 2);
                    ulonglong2 w  = *(const ulonglong2*)(wrow + kk * 8);
                    fma2(acc[0][0], pa.x, w.x); fma2(acc[0][1], pa.x, w.y);
                    fma2(acc[1][0], pa.y, w.x); fma2(acc[1][1], pa.y, w.y);
                    fma2(acc[2][0], pb.x, w.x); fma2(acc[2][1], pb.x, w.y);
                    fma2(acc[3][0], pb.y, w.x); fma2(acc[3][1], pb.y, w.y);
                }
                c0 = p0; c1 = p1; c2 = p2; c3 = p3;
            }
            __syncwarp();   // all lanes done reading Aw before partials overwrite it
#pragma unroll
            for (int mi = 0; mi < 4; mi++)
#pragma unroll
                for (int p = 0; p < 2; p++) {
                    float2 f = unp(acc[mi][p]);
                    int idx = (m0 + mi) * 8 + ng * 4 + p * 2;
                    Rw[idx] = f.x; Rw[idx + 1] = f.y;
                }
            __syncthreads();
#pragma unroll
            for (int j = 0; j < 2; j++) {
                int idx = tid + 256 * j;
                int m = idx >> 3, nl = idx & 7;
                float s = b1[nA0 + nl];
#pragma unroll
                for (int w = 0; w < 8; w++) s += Rall[w * 1024 + idx];
                __stcg(&g_inter[m * CC + nA0 + nl], gelu_t(s));
            }
        }
        gbar(&barc);

        // ---------- phase B: cont = inter @ W2 + b2; block owns 16 cols ----------
        {
            ull acc[4][4];
#pragma unroll
            for (int i = 0; i < 4; i++)
#pragma unroll
                for (int j = 0; j < 4; j++) acc[i][j] = 0;

            const float* base0 = g_inter + (size_t)lane * CC + k0;
            const float* base1 = g_inter + (size_t)(lane + 32) * CC + k0;
            float4 c0 = ldcg4(base0), c1 = ldcg4(base0 + 4);
            float4 c2 = ldcg4(base1), c3 = ldcg4(base1 + 4);

            const float* wB = sW2 + (size_t)k0 * 16 + ng * 8;

            for (int kc = 0; kc < 16; kc++) {
                float4 p0, p1, p2, p3;
                if (kc < 15) {
                    const float* q0 = base0 + (kc + 1) * 8;
                    const float* q1 = base1 + (kc + 1) * 8;
                    p0 = ldcg4(q0); p1 = ldcg4(q0 + 4);
                    p2 = ldcg4(q1); p3 = ldcg4(q1 + 4);
                } else {
                    p0 = c0; p1 = c1; p2 = c2; p3 = c3;
                }
                __syncwarp();
                const int m2 = lane + 32;
                Aw[0 * 64 + lane] = dup2(c0.x); Aw[1 * 64 + lane] = dup2(c0.y);
                Aw[2 * 64 + lane] = dup2(c0.z); Aw[3 * 64 + lane] = dup2(c0.w);
                Aw[4 * 64 + lane] = dup2(c1.x); Aw[5 * 64 + lane] = dup2(c1.y);
                Aw[6 * 64 + lane] = dup2(c1.z); Aw[7 * 64 + lane] = dup2(c1.w);
                Aw[0 * 64 + m2] = dup2(c2.x);   Aw[1 * 64 + m2] = dup2(c2.y);
                Aw[2 * 64 + m2] = dup2(c2.z);   Aw[3 * 64 + m2] = dup2(c2.w);
                Aw[4 * 64 + m2] = dup2(c3.x);   Aw[5 * 64 + m2] = dup2(c3.y);
                Aw[6 * 64 + m2] = dup2(c3.z);   Aw[7 * 64 + m2] = dup2(c3.w);
                __syncwarp();
                const float* wrow = wB + (size_t)kc * 128;  // 8 k-rows x 16 floats
#pragma unroll
                for (int kk = 0; kk < 8; kk++) {
                    ulonglong2 pa = *(const ulonglong2*)(Aw + kk * 64 + m0);
                    ulonglong2 pb = *(const ulonglong2*)(Aw + kk * 64 + m0 + 2);
                    const float* wr = wrow + kk * 16;
                    ulonglong2 w0 = *(const ulonglong2*)(wr);
                    ulonglong2 w1 = *(const ulonglong2*)(wr + 4);
                    ull av[4] = {pa.x, pa.y, pb.x, pb.y};
#pragma unroll
                    for (int mi = 0; mi < 4; mi++) {
                        fma2(acc[mi][0], av[mi], w0.x);
                        fma2(acc[mi][1], av[mi], w0.y);
                        fma2(acc[mi][2], av[mi], w1.x);
                        fma2(acc[mi][3], av[mi], w1.y);
                    }
                }
                c0 = p0; c1 = p1; c2 = p2; c3 = p3;
            }
            __syncwarp();
#pragma unroll
            for (int mi = 0; mi < 4; mi++)
#pragma unroll
                for (int np = 0; np < 4; np++) {
                    float2 f = unp(acc[mi][np]);
                    int idx = (m0 + mi) * 16 + ng * 8 + np * 2;
                    Rw[idx] = f.x; Rw[idx + 1] = f.y;
                }
            __syncthreads();
#pragma unroll
            for (int j = 0; j < 4; j++) {
                int idx = tid + 256 * j;
                int m = idx >> 4, nl = idx & 15;
                float s = b2[nB0 + nl];
#pragma unroll
                for (int w = 0; w < 8; w++) s += Rall[w * 1024 + idx];
                __stcg(&g_cont[m * (4 * DD) + nB0 + nl], s);
            }
        }
        gbar(&barc);

        // ---------- phase C: gates + LN + state update (blocks 0..63) ----------
        if (b < NN) {
            float mval = mask[(size_t)b * SS + t];
            float vv[2];
#pragma unroll
            for (int h = 0; h < 2; h++) {
                int d = tid + 256 * h;
                const float* cb = g_cont + b * (4 * DD);
                float c0 = __ldcg(cb + d);
                float c1 = __ldcg(cb + 512 + d);
                float c2 = __ldcg(cb + 1024 + d);
                float c3 = __ldcg(cb + 1536 + d);
                float h0 = g_ht[b * DD + d];
                float x0 = g_X[((size_t)b * SS + t) * DD + d];
                vv[h] = sigm(c0) * h0 + sigm(c1) * x0 + sigm(c2) * c3;
            }
            float mean = bsum(vv[0] + vv[1], scC) * (1.f / DD);
            float e0 = vv[0] - mean, e1 = vv[1] - mean;
            float var = bsum(e0 * e0 + e1 * e1, scC) * (1.f / DD);
            float rs = rsqrtf(var + 1e-5f);
#pragma unroll
            for (int h = 0; h < 2; h++) {
                int d = tid + 256 * h;
                float hn = (vv[h] - mean) * rs * lng[d] + lnb[d];
                g_ht[b * DD + d] = hn;
                out[((size_t)b * SS + t) * DD + d] = hn * mval;
                g_gs[b * DD + d] = mval * hn + (1.f - mval) * g_gs[b * DD + d];
            }
        }
        gbar(&barc);
    }

    // final global_state
    if (b < NN) {
#pragma unroll
        for (int h = 0; h < 2; h++) {
            int d = tid + 256 * h;
            out[(size_t)NN * SS * DD + b * DD + d] = g_gs[b * DD + d];
        }
    }
}

extern "C" void kernel_launch(void* const* d_in, const int* in_sizes, int n_in,
                              void* d_out, int out_size) {
    (void)in_sizes; (void)n_in; (void)out_size;
    const float* seq   = (const float*)d_in[0];
    const float* mask  = (const float*)d_in[1];
    const float* START = (const float*)d_in[2];
    const float* Wi    = (const float*)d_in[3];
    const float* bi    = (const float*)d_in[4];
    const float* W1    = (const float*)d_in[5];
    const float* b1    = (const float*)d_in[6];
    const float* W2    = (const float*)d_in[7];
    const float* b2    = (const float*)d_in[8];
    const float* lng   = (const float*)d_in[9];
    const float* lnb   = (const float*)d_in[10];
    float* out = (float*)d_out;

    static bool attr_done = false;
    if (!attr_done) {
        cudaFuncSetAttribute(k_recur, cudaFuncAttributeMaxDynamicSharedMemorySize,
                             SMEM_RECUR);
        attr_done = true;
    }

    dim3 g1(DD / 64, (NN * SS) / 64);
    k_init_gemm<<<g1, 256>>>(seq, mask, Wi, bi);
    k_ln<<<NN * SS, 128>>>(lng, lnb, mask);
    k_recur<<<GRID, NTHREADS, SMEM_RECUR>>>(mask, START, W1, b1, W2, b2, lng, lnb, out);
}

// round 14
// speedup vs baseline: 2.0578x; 1.1708x over previous
#include <cuda_runtime.h>

#define NN 64
#define SS 512
#define DD 512
#define CC 1024
#define GRID 128
#define NTHREADS 256

// dynamic smem layout for k_main (bytes):
//   [0,      32768)  A2 staging: 8 warps x 512 ull  (also reused as GEMM tiles in prologue)
//   [32768,  65536)  sW1: 1024 rows x 8 floats   (block's W1 column slice)
//   [65536, 131072)  sW2: 1024 rows x 16 floats  (block's W2 column slice)
#define SMEM_MAIN (32768 + 32768 + 65536)

// ---------------- device scratch (static, no allocations) ----------------
__device__ float g_X[(size_t)NN * SS * DD];   // LN'd masked inputs (64 MB)
__device__ float g_ht[NN * DD];
__device__ float g_gs[NN * DD];
__device__ float g_inter[NN * CC];
__device__ float g_cont[NN * 4 * DD];
__device__ unsigned g_cnt;
__device__ unsigned g_sense;

typedef unsigned long long ull;

__device__ __forceinline__ void fma2(ull& d, ull a, ull b) {
    asm("fma.rn.f32x2 %0, %1, %2, %0;" : "+l"(d) : "l"(a), "l"(b));
}
__device__ __forceinline__ ull dup2(float f) {
    ull r; asm("mov.b64 %0, {%1, %1};" : "=l"(r) : "f"(f)); return r;
}
__device__ __forceinline__ float2 unp(ull v) {
    float2 r; asm("mov.b64 {%0, %1}, %2;" : "=f"(r.x), "=f"(r.y) : "l"(v)); return r;
}
__device__ __forceinline__ float sigm(float x) { return 1.f / (1.f + expf(-x)); }
__device__ __forceinline__ float gelu_t(float x) {
    float u = x + 0.044715f * x * x * x;
    return 0.5f * x * (1.f + tanhf(0.7978845608028654f * u));
}
__device__ __forceinline__ float4 ldcg4(const float* p) {
    return __ldcg((const float4*)p);
}

// barrier-state reset: must run before k_main each launch (graph-replay safe)
__global__ void k_reset() { g_cnt = 0; g_sense = 0; }

// Fence-free global barrier: release-atomic arrive, relaxed-poll + single
// acquire-load on success. No membar.gl => L1D is never flushed.
__device__ __forceinline__ void gbar(unsigned* barc) {
    __syncthreads();
    unsigned target = ++(*barc);
    if (threadIdx.x == 0) {
        unsigned prev;
        asm volatile("atom.release.gpu.add.u32 %0, [%1], 1;"
                     : "=r"(prev) : "l"(&g_cnt) : "memory");
        if (prev == GRID - 1) {
            asm volatile("st.relaxed.gpu.u32 [%0], %1;"
                         :: "l"(&g_cnt), "r"(0u) : "memory");
            asm volatile("st.release.gpu.u32 [%0], %1;"
                         :: "l"(&g_sense), "r"(target) : "memory");
        } else {
            unsigned s;
            do {
                asm volatile("ld.relaxed.gpu.u32 %0, [%1];"
                             : "=r"(s) : "l"(&g_sense) : "memory");
            } while (s < target);
            asm volatile("ld.acquire.gpu.u32 %0, [%1];"
                         : "=r"(s) : "l"(&g_sense) : "memory");
        }
    }
    __syncthreads();
}

// block sum over 256 threads (8 warps)
__device__ __forceinline__ float bsum(float v, float* sc) {
    int lane = threadIdx.x & 31, w = threadIdx.x >> 5;
#pragma unroll
    for (int o = 16; o; o >>= 1) v += __shfl_xor_sync(0xffffffffu, v, o);
    if (lane == 0) sc[w] = v;
    __syncthreads();
    if (w == 0) {
        float s = (lane < 8) ? sc[lane] : 0.f;
#pragma unroll
        for (int o = 4; o; o >>= 1) s += __shfl_xor_sync(0xffffffffu, s, o);
        if (lane == 0) sc[8] = s;
    }
    __syncthreads();
    float r = sc[8];
    __syncthreads();
    return r;
}

__global__ void __launch_bounds__(NTHREADS, 1) k_main(
    const float* __restrict__ seq, const float* __restrict__ mask,
    const float* __restrict__ START,
    const float* __restrict__ Wi, const float* __restrict__ bi,
    const float* __restrict__ W1, const float* __restrict__ b1,
    const float* __restrict__ W2, const float* __restrict__ b2,
    const float* __restrict__ lng, const float* __restrict__ lnb,
    float* __restrict__ out)
{
    extern __shared__ char smch[];
    ull* const A2 = (ull*)smch;                         // 8 x 512 ull (32 KB)
    float* const sW1 = (float*)(smch + 32768);          // [1024][8]  (32 KB)
    float* const sW2 = (float*)(smch + 65536);          // [1024][16] (64 KB)
    __shared__ float scC[16];

    const int tid = threadIdx.x;
    const int lane = tid & 31;
    const int warp = tid >> 5;
    const int b = blockIdx.x;
    unsigned barc = 0;

    const int nA0 = b * 8;
    const int nB0 = b * 16;

    // ---- one-time: copy this block's weight slices into smem ----
    for (int i = tid; i < CC * 2; i += NTHREADS) {      // sW1: 2048 float4
        int row = i >> 1, half = i & 1;
        *(float4*)(sW1 + (size_t)row * 8 + half * 4) =
            *(const float4*)(W1 + (size_t)row * CC + nA0 + half * 4);
    }
    for (int i = tid; i < CC * 4; i += NTHREADS) {      // sW2: 4096 float4
        int row = i >> 2, q = i & 3;
        *(float4*)(sW2 + (size_t)row * 16 + q * 4) =
            *(const float4*)(W2 + (size_t)row * (4 * DD) + nB0 + q * 4);
    }

    // =============== prologue 1: g_X stripe = (seq*mask) @ Wi + bi ===============
    // block b owns rows [b*256, b*256+256): 4 row-tiles x 8 col-tiles of 64x64
    {
        float* const As = (float*)smch;        // 16x64 floats (4 KB), aliases A2
        float* const Bs = As + 16 * 64;        // 16x64 floats (4 KB)
        const int lm = tid >> 2;               // row for A-load (0..63)
        const int kq = (tid & 3) * 4;          // k-quad for A-load
        const int bk = tid >> 4;               // k for B-load (0..15)
        const int bn = (tid & 15) * 4;         // n-quad for B-load
        const int ty = tid >> 4;               // m-group for compute
        const int tx = tid & 15;               // n-group for compute

        for (int rt = 0; rt < 4; rt++) {
            const int row0 = b * 256 + rt * 64;
            const float mval = mask[row0 + lm];
            for (int ct = 0; ct < 8; ct++) {
                const int n0 = ct * 64;
                float acc[4][4];
#pragma unroll
                for (int i = 0; i < 4; i++)
#pragma unroll
                    for (int j = 0; j < 4; j++) acc[i][j] = 0.f;

                for (int kt = 0; kt < DD / 16; kt++) {
                    float4 a = *(const float4*)&seq[(size_t)(row0 + lm) * DD + kt * 16 + kq];
                    As[(kq + 0) * 64 + lm] = a.x * mval;
                    As[(kq + 1) * 64 + lm] = a.y * mval;
                    As[(kq + 2) * 64 + lm] = a.z * mval;
                    As[(kq + 3) * 64 + lm] = a.w * mval;
                    *(float4*)&Bs[bk * 64 + bn] =
                        *(const float4*)&Wi[(size_t)(kt * 16 + bk) * DD + n0 + bn];
                    __syncthreads();
#pragma unroll
                    for (int k = 0; k < 16; k++) {
                        float4 av = *(const float4*)&As[k * 64 + ty * 4];
                        float4 bv = *(const float4*)&Bs[k * 64 + tx * 4];
                        float am[4] = {av.x, av.y, av.z, av.w};
                        float bb[4] = {bv.x, bv.y, bv.z, bv.w};
#pragma unroll
                        for (int i = 0; i < 4; i++)
#pragma unroll
                            for (int j = 0; j < 4; j++) acc[i][j] += am[i] * bb[j];
                    }
                    __syncthreads();
                }
#pragma unroll
                for (int i = 0; i < 4; i++)
#pragma unroll
                    for (int j = 0; j < 4; j++) {
                        int n = n0 + tx * 4 + j;
                        g_X[(size_t)(row0 + ty * 4 + i) * DD + n] = acc[i][j] + bi[n];
                    }
            }
        }
        __syncthreads();
    }

    // =============== prologue 2: warp-parallel LN of the same 256 rows ===============
    {
        const float4 g0 = *(const float4*)(lng + lane * 16);
        const float4 g1 = *(const float4*)(lng + lane * 16 + 4);
        const float4 g2 = *(const float4*)(lng + lane * 16 + 8);
        const float4 g3 = *(const float4*)(lng + lane * 16 + 12);
        const float4 h0 = *(const float4*)(lnb + lane * 16);
        const float4 h1 = *(const float4*)(lnb + lane * 16 + 4);
        const float4 h2 = *(const float4*)(lnb + lane * 16 + 8);
        const float4 h3 = *(const float4*)(lnb + lane * 16 + 12);

        for (int r = 0; r < 32; r++) {
            const int row = b * 256 + warp * 32 + r;
            float* xp = g_X + (size_t)row * DD + lane * 16;
            float4 v0 = *(float4*)(xp);
            float4 v1 = *(float4*)(xp + 4);
            float4 v2 = *(float4*)(xp + 8);
            float4 v3 = *(float4*)(xp + 12);

            float s = v0.x + v0.y + v0.z + v0.w + v1.x + v1.y + v1.z + v1.w
                    + v2.x + v2.y + v2.z + v2.w + v3.x + v3.y + v3.z + v3.w;
#pragma unroll
            for (int o = 16; o; o >>= 1) s += __shfl_xor_sync(0xffffffffu, s, o);
            float mean = s * (1.f / DD);

            float q =
                (v0.x-mean)*(v0.x-mean) + (v0.y-mean)*(v0.y-mean) +
                (v0.z-mean)*(v0.z-mean) + (v0.w-mean)*(v0.w-mean) +
                (v1.x-mean)*(v1.x-mean) + (v1.y-mean)*(v1.y-mean) +
                (v1.z-mean)*(v1.z-mean) + (v1.w-mean)*(v1.w-mean) +
                (v2.x-mean)*(v2.x-mean) + (v2.y-mean)*(v2.y-mean) +
                (v2.z-mean)*(v2.z-mean) + (v2.w-mean)*(v2.w-mean) +
                (v3.x-mean)*(v3.x-mean) + (v3.y-mean)*(v3.y-mean) +
                (v3.z-mean)*(v3.z-mean) + (v3.w-mean)*(v3.w-mean);
#pragma unroll
            for (int o = 16; o; o >>= 1) q += __shfl_xor_sync(0xffffffffu, q, o);
            float rs = rsqrtf(q * (1.f / DD) + 1e-5f);

            float mval = mask[row];
            v0.x = ((v0.x-mean)*rs*g0.x + h0.x)*mval; v0.y = ((v0.y-mean)*rs*g0.y + h0.y)*mval;
            v0.z = ((v0.z-mean)*rs*g0.z + h0.z)*mval; v0.w = ((v0.w-mean)*rs*g0.w + h0.w)*mval;
            v1.x = ((v1.x-mean)*rs*g1.x + h1.x)*mval; v1.y = ((v1.y-mean)*rs*g1.y + h1.y)*mval;
            v1.z = ((v1.z-mean)*rs*g1.z + h1.z)*mval; v1.w = ((v1.w-mean)*rs*g1.w + h1.w)*mval;
            v2.x = ((v2.x-mean)*rs*g2.x + h2.x)*mval; v2.y = ((v2.y-mean)*rs*g2.y + h2.y)*mval;
            v2.z = ((v2.z-mean)*rs*g2.z + h2.z)*mval; v2.w = ((v2.w-mean)*rs*g2.w + h2.w)*mval;
            v3.x = ((v3.x-mean)*rs*g3.x + h3.x)*mval; v3.y = ((v3.y-mean)*rs*g3.y + h3.y)*mval;
            v3.z = ((v3.z-mean)*rs*g3.z + h3.z)*mval; v3.w = ((v3.w-mean)*rs*g3.w + h3.w)*mval;
            *(float4*)(xp)      = v0;
            *(float4*)(xp + 4)  = v1;
            *(float4*)(xp + 8)  = v2;
            *(float4*)(xp + 12) = v3;
        }
    }

    // init carry
    if (b < NN) {
#pragma unroll
        for (int j = 0; j < 2; j++) {
            int d = tid + 256 * j;
            float s = START[d];
            g_ht[b * DD + d] = s;
            g_gs[b * DD + d] = s;
        }
    }
    gbar(&barc);   // all stripes of g_X + carries visible; smem tiles free for staging

    // =============== scan ===============
    const int mg = lane & 15;
    const int ng = lane >> 4;
    const int k0 = warp * 128;
    ull* const Aw = A2 + warp * 512;
    float* const Rw = (float*)Aw;          // this warp's 1024-float partial slot
    float* const Rall = (float*)A2;
    // conflict-free m-remap: lane's 4 accumulator rows
    const int mrow0 = 2 * mg, mrow1 = 2 * mg + 1, mrow2 = 2 * mg + 32, mrow3 = 2 * mg + 33;

    for (int t = 0; t < SS; t++) {
        // ---------- phase A: inter = gelu(cat @ W1 + b1); block owns 8 cols ----------
        {
            ull acc[4][2];
#pragma unroll
            for (int i = 0; i < 4; i++) { acc[i][0] = 0; acc[i][1] = 0; }

            const float *base0, *base1;
            if (warp < 4) {
                base0 = g_ht + (size_t)lane * DD + k0;
                base1 = g_ht + (size_t)(lane + 32) * DD + k0;
            } else {
                size_t off = (size_t)t * DD + (k0 - 512);
                base0 = g_X + (size_t)lane * SS * DD + off;
                base1 = g_X + (size_t)(lane + 32) * SS * DD + off;
            }
            float4 c0 = ldcg4(base0), c1 = ldcg4(base0 + 4);
            float4 c2 = ldcg4(base1), c3 = ldcg4(base1 + 4);

            const float* wA = sW1 + (size_t)k0 * 8 + ng * 4;

            for (int kc = 0; kc < 16; kc++) {
                float4 p0, p1, p2, p3;
                if (kc < 15) {
                    const float* q0 = base0 + (kc + 1) * 8;
                    const float* q1 = base1 + (kc + 1) * 8;
                    p0 = ldcg4(q0); p1 = ldcg4(q0 + 4);
                    p2 = ldcg4(q1); p3 = ldcg4(q1 + 4);
                } else {
                    p0 = c0; p1 = c1; p2 = c2; p3 = c3;
                }
                __syncwarp();
                const int m2 = lane + 32;
                Aw[0 * 64 + lane] = dup2(c0.x); Aw[1 * 64 + lane] = dup2(c0.y);
                Aw[2 * 64 + lane] = dup2(c0.z); Aw[3 * 64 + lane] = dup2(c0.w);
                Aw[4 * 64 + lane] = dup2(c1.x); Aw[5 * 64 + lane] = dup2(c1.y);
                Aw[6 * 64 + lane] = dup2(c1.z); Aw[7 * 64 + lane] = dup2(c1.w);
                Aw[0 * 64 + m2] = dup2(c2.x);   Aw[1 * 64 + m2] = dup2(c2.y);
                Aw[2 * 64 + m2] = dup2(c2.z);   Aw[3 * 64 + m2] = dup2(c2.w);
                Aw[4 * 64 + m2] = dup2(c3.x);   Aw[5 * 64 + m2] = dup2(c3.y);
                Aw[6 * 64 + m2] = dup2(c3.z);   Aw[7 * 64 + m2] = dup2(c3.w);
                __syncwarp();
                const float* wrow = wA + (size_t)kc * 64;   // 8 k-rows x 8 floats
#pragma unroll
                for (int kk = 0; kk < 8; kk++) {
                    // conflict-free: 16 lanes read 2x16B contiguous (m = 2mg,2mg+1 / +32)
                    ulonglong2 pa = *(const ulonglong2*)(Aw + kk * 64 + 2 * mg);
                    ulonglong2 pb = *(const ulonglong2*)(Aw + kk * 64 + 32 + 2 * mg);
                    ulonglong2 w  = *(const ulonglong2*)(wrow + kk * 8);
                    fma2(acc[0][0], pa.x, w.x); fma2(acc[0][1], pa.x, w.y);
                    fma2(acc[1][0], pa.y, w.x); fma2(acc[1][1], pa.y, w.y);
                    fma2(acc[2][0], pb.x, w.x); fma2(acc[2][1], pb.x, w.y);
                    fma2(acc[3][0], pb.y, w.x); fma2(acc[3][1], pb.y, w.y);
                }
                c0 = p0; c1 = p1; c2 = p2; c3 = p3;
            }
            __syncwarp();   // all lanes done reading Aw before partials overwrite it
            {
                const int mr[4] = {mrow0, mrow1, mrow2, mrow3};
#pragma unroll
                for (int mi = 0; mi < 4; mi++)
#pragma unroll
                    for (int p = 0; p < 2; p++) {
                        float2 f = unp(acc[mi][p]);
                        int idx = mr[mi] * 8 + ng * 4 + p * 2;
                        Rw[idx] = f.x; Rw[idx + 1] = f.y;
                    }
            }
            __syncthreads();
#pragma unroll
            for (int j = 0; j < 2; j++) {
                int idx = tid + 256 * j;
                int m = idx >> 3, nl = idx & 7;
                float s = b1[nA0 + nl];
#pragma unroll
                for (int w = 0; w < 8; w++) s += Rall[w * 1024 + idx];
                __stcg(&g_inter[m * CC + nA0 + nl], gelu_t(s));
            }
        }
        gbar(&barc);

        // ---------- phase B: cont = inter @ W2 + b2; block owns 16 cols ----------
        {
            ull acc[4][4];
#pragma unroll
            for (int i = 0; i < 4; i++)
#pragma unroll
                for (int j = 0; j < 4; j++) acc[i][j] = 0;

            const float* base0 = g_inter + (size_t)lane * CC + k0;
            const float* base1 = g_inter + (size_t)(lane + 32) * CC + k0;
            float4 c0 = ldcg4(base0), c1 = ldcg4(base0 + 4);
            float4 c2 = ldcg4(base1), c3 = ldcg4(base1 + 4);

            const float* wB = sW2 + (size_t)k0 * 16 + ng * 8;

            for (int kc = 0; kc < 16; kc++) {
                float4 p0, p1, p2, p3;
                if (kc < 15) {
                    const float* q0 = base0 + (kc + 1) * 8;
                    const float* q1 = base1 + (kc + 1) * 8;
                    p0 = ldcg4(q0); p1 = ldcg4(q0 + 4);
                    p2 = ldcg4(q1); p3 = ldcg4(q1 + 4);
                } else {
                    p0 = c0; p1 = c1; p2 = c2; p3 = c3;
                }
                __syncwarp();
                const int m2 = lane + 32;
                Aw[0 * 64 + lane] = dup2(c0.x); Aw[1 * 64 + lane] = dup2(c0.y);
                Aw[2 * 64 + lane] = dup2(c0.z); Aw[3 * 64 + lane] = dup2(c0.w);
                Aw[4 * 64 + lane] = dup2(c1.x); Aw[5 * 64 + lane] = dup2(c1.y);
                Aw[6 * 64 + lane] = dup2(c1.z); Aw[7 * 64 + lane] = dup2(c1.w);
                Aw[0 * 64 + m2] = dup2(c2.x);   Aw[1 * 64 + m2] = dup2(c2.y);
                Aw[2 * 64 + m2] = dup2(c2.z);   Aw[3 * 64 + m2] = dup2(c2.w);
                Aw[4 * 64 + m2] = dup2(c3.x);   Aw[5 * 64 + m2] = dup2(c3.y);
                Aw[6 * 64 + m2] = dup2(c3.z);   Aw[7 * 64 + m2] = dup2(c3.w);
                __syncwarp();
                const float* wrow = wB + (size_t)kc * 128;  // 8 k-rows x 16 floats
#pragma unroll
                for (int kk = 0; kk < 8; kk++) {
                    ulonglong2 pa = *(const ulonglong2*)(Aw + kk * 64 + 2 * mg);
                    ulonglong2 pb = *(const ulonglong2*)(Aw + kk * 64 + 32 + 2 * mg);
                    const float* wr = wrow + kk * 16;
                    ulonglong2 w0 = *(const ulonglong2*)(wr);
                    ulonglong2 w1 = *(const ulonglong2*)(wr + 4);
                    ull av[4] = {pa.x, pa.y, pb.x, pb.y};
#pragma unroll
                    for (int mi = 0; mi < 4; mi++) {
                        fma2(acc[mi][0], av[mi], w0.x);
                        fma2(acc[mi][1], av[mi], w0.y);
                        fma2(acc[mi][2], av[mi], w1.x);
                        fma2(acc[mi][3], av[mi], w1.y);
                    }
                }
                c0 = p0; c1 = p1; c2 = p2; c3 = p3;
            }
            __syncwarp();
            {
                const int mr[4] = {mrow0, mrow1, mrow2, mrow3};
#pragma unroll
                for (int mi = 0; mi < 4; mi++)
#pragma unroll
                    for (int np = 0; np < 4; np++) {
                        float2 f = unp(acc[mi][np]);
                        int idx = mr[mi] * 16 + ng * 8 + np * 2;
                        Rw[idx] = f.x; Rw[idx + 1] = f.y;
                    }
            }
            __syncthreads();
#pragma unroll
            for (int j = 0; j < 4; j++) {
                int idx = tid + 256 * j;
                int m = idx >> 4, nl = idx & 15;
                float s = b2[nB0 + nl];
#pragma unroll
                for (int w = 0; w < 8; w++) s += Rall[w * 1024 + idx];
                __stcg(&g_cont[m * (4 * DD) + nB0 + nl], s);
            }
        }
        gbar(&barc);

        // ---------- phase C: gates + LN + state update (blocks 0..63) ----------
        if (b < NN) {
            float mval = mask[(size_t)b * SS + t];
            float vv[2];
#pragma unroll
            for (int h = 0; h < 2; h++) {
                int d = tid + 256 * h;
                const float* cb = g_cont + b * (4 * DD);
                float c0 = __ldcg(cb + d);
                float c1 = __ldcg(cb + 512 + d);
                float c2 = __ldcg(cb + 1024 + d);
                float c3 = __ldcg(cb + 1536 + d);
                float h0 = g_ht[b * DD + d];
                float x0 = g_X[((size_t)b * SS + t) * DD + d];
                vv[h] = sigm(c0) * h0 + sigm(c1) * x0 + sigm(c2) * c3;
            }
            float mean = bsum(vv[0] + vv[1], scC) * (1.f / DD);
            float e0 = vv[0] - mean, e1 = vv[1] - mean;
            float var = bsum(e0 * e0 + e1 * e1, scC) * (1.f / DD);
            float rs = rsqrtf(var + 1e-5f);
#pragma unroll
            for (int h = 0; h < 2; h++) {
                int d = tid + 256 * h;
                float hn = (vv[h] - mean) * rs * lng[d] + lnb[d];
                g_ht[b * DD + d] = hn;
                out[((size_t)b * SS + t) * DD + d] = hn * mval;
                g_gs[b * DD + d] = mval * hn + (1.f - mval) * g_gs[b * DD + d];
            }
        }
        gbar(&barc);
    }

    // final global_state
    if (b < NN) {
#pragma unroll
        for (int h = 0; h < 2; h++) {
            int d = tid + 256 * h;
            out[(size_t)NN * SS * DD + b * DD + d] = g_gs[b * DD + d];
        }
    }
}

extern "C" void kernel_launch(void* const* d_in, const int* in_sizes, int n_in,
                              void* d_out, int out_size) {
    (void)in_sizes; (void)n_in; (void)out_size;
    const float* seq   = (const float*)d_in[0];
    const float* mask  = (const float*)d_in[1];
    const float* START = (const float*)d_in[2];
    const float* Wi    = (const float*)d_in[3];
    const float* bi    = (const float*)d_in[4];
    const float* W1    = (const float*)d_in[5];
    const float* b1    = (const float*)d_in[6];
    const float* W2    = (const float*)d_in[7];
    const float* b2    = (const float*)d_in[8];
    const float* lng   = (const float*)d_in[9];
    const float* lnb   = (const float*)d_in[10];
    float* out = (float*)d_out;

    static bool attr_done = false;
    if (!attr_done) {
        cudaFuncSetAttribute(k_main, cudaFuncAttributeMaxDynamicSharedMemorySize,
                             SMEM_MAIN);
        attr_done = true;
    }

    k_reset<<<1, 1>>>();
    k_main<<<GRID, NTHREADS, SMEM_MAIN>>>(seq, mask, START, Wi, bi,
                                          W1, b1, W2, b2, lng, lnb, out);
}

// round 15
// speedup vs baseline: 2.4749x; 1.2027x over previous
#include <cuda_runtime.h>

#define NN 64
#define SS 512
#define DD 512
#define CC 1024
#define GRID 128
#define NTHREADS 512

// dynamic smem layout for k_main (bytes):
//   [0,      73728)   per-warp region: 16 warps x 1152 floats (4608 B)
//                       staging double-buffer [0,1024) floats, partials [0,1088)
//                       (prologue: 2 teams x 2048 floats of GEMM tiles)
//   [73728, 106496)   sW1: 1024 rows x 8 floats   (block's W1 column slice)
//   [106496,172032)   sW2: 1024 rows x 16 floats  (block's W2 column slice)
#define PWS 1152
#define SMEM_MAIN (16 * PWS * 4 + 32768 + 65536)

// ---------------- device scratch (static, no allocations) ----------------
__device__ float g_X[(size_t)NN * SS * DD];   // LN'd masked inputs (64 MB)
__device__ float g_ht[NN * DD];
__device__ float g_gs[NN * DD];
__device__ float g_inter[NN * CC];
__device__ float g_cont[NN * 4 * DD];
__device__ unsigned g_cnt;
__device__ unsigned g_sense;

typedef unsigned long long ull;

__device__ __forceinline__ void fma2(ull& d, ull a, ull b) {
    asm("fma.rn.f32x2 %0, %1, %2, %0;" : "+l"(d) : "l"(a), "l"(b));
}
__device__ __forceinline__ ull dup2(float f) {
    ull r; asm("mov.b64 %0, {%1, %1};" : "=l"(r) : "f"(f)); return r;
}
__device__ __forceinline__ float2 unp(ull v) {
    float2 r; asm("mov.b64 {%0, %1}, %2;" : "=f"(r.x), "=f"(r.y) : "l"(v)); return r;
}
__device__ __forceinline__ float sigm(float x) { return 1.f / (1.f + expf(-x)); }
__device__ __forceinline__ float gelu_t(float x) {
    float u = x + 0.044715f * x * x * x;
    return 0.5f * x * (1.f + tanhf(0.7978845608028654f * u));
}
__device__ __forceinline__ float4 ldcg4(const float* p) {
    return __ldcg((const float4*)p);
}

// barrier-state reset: must run before k_main each launch (graph-replay safe)
__global__ void k_reset() { g_cnt = 0; g_sense = 0; }

// Fence-free global barrier (no membar.gl => no L1D flush)
__device__ __forceinline__ void gbar(unsigned* barc) {
    __syncthreads();
    unsigned target = ++(*barc);
    if (threadIdx.x == 0) {
        unsigned prev;
        asm volatile("atom.release.gpu.add.u32 %0, [%1], 1;"
                     : "=r"(prev) : "l"(&g_cnt) : "memory");
        if (prev == GRID - 1) {
            asm volatile("st.relaxed.gpu.u32 [%0], %1;"
                         :: "l"(&g_cnt), "r"(0u) : "memory");
            asm volatile("st.release.gpu.u32 [%0], %1;"
                         :: "l"(&g_sense), "r"(target) : "memory");
        } else {
            unsigned s;
            do {
                asm volatile("ld.relaxed.gpu.u32 %0, [%1];"
                             : "=r"(s) : "l"(&g_sense) : "memory");
            } while (s < target);
            asm volatile("ld.acquire.gpu.u32 %0, [%1];"
                         : "=r"(s) : "l"(&g_sense) : "memory");
        }
    }
    __syncthreads();
}

// block sum over 512 threads (16 warps)
__device__ __forceinline__ float bsum512(float v, float* sc) {
    int lane = threadIdx.x & 31, w = threadIdx.x >> 5;
#pragma unroll
    for (int o = 16; o; o >>= 1) v += __shfl_xor_sync(0xffffffffu, v, o);
    if (lane == 0) sc[w] = v;
    __syncthreads();
    if (w == 0) {
        float s = (lane < 16) ? sc[lane] : 0.f;
#pragma unroll
        for (int o = 8; o; o >>= 1) s += __shfl_xor_sync(0xffffffffu, s, o);
        if (lane == 0) sc[16] = s;
    }
    __syncthreads();
    float r = sc[16];
    __syncthreads();
    return r;
}

__global__ void __launch_bounds__(NTHREADS, 1) k_main(
    const float* __restrict__ seq, const float* __restrict__ mask,
    const float* __restrict__ START,
    const float* __restrict__ Wi, const float* __restrict__ bi,
    const float* __restrict__ W1, const float* __restrict__ b1,
    const float* __restrict__ W2, const float* __restrict__ b2,
    const float* __restrict__ lng, const float* __restrict__ lnb,
    float* __restrict__ out)
{
    extern __shared__ char smch[];
    float* const Rall = (float*)smch;                    // 16 x PWS floats
    float* const sW1 = (float*)(smch + 16 * PWS * 4);    // [1024][8]
    float* const sW2 = (float*)(smch + 16 * PWS * 4 + 32768);  // [1024][16]
    __shared__ float scC[32];

    const int tid = threadIdx.x;
    const int lane = tid & 31;
    const int warp = tid >> 5;
    const int b = blockIdx.x;
    unsigned barc = 0;

    const int nA0 = b * 8;
    const int nB0 = b * 16;

    // ---- one-time: copy this block's weight slices into smem ----
    for (int i = tid; i < CC * 2; i += NTHREADS) {      // sW1: 2048 float4
        int row = i >> 1, half = i & 1;
        *(float4*)(sW1 + (size_t)row * 8 + half * 4) =
            *(const float4*)(W1 + (size_t)row * CC + nA0 + half * 4);
    }
    for (int i = tid; i < CC * 4; i += NTHREADS) {      // sW2: 4096 float4
        int row = i >> 2, q = i & 3;
        *(float4*)(sW2 + (size_t)row * 16 + q * 4) =
            *(const float4*)(W2 + (size_t)row * (4 * DD) + nB0 + q * 4);
    }

    // =============== prologue 1: g_X stripe = (seq*mask) @ Wi + bi ===============
    // two 256-thread teams (warps 0-7 / 8-15) each handle 2 of 4 row-tiles
    {
        const int team = warp >> 3;
        const int ttid = tid & 255;
        float* const As = (float*)smch + team * 2048;   // 1024 floats
        float* const Bs = As + 1024;                    // 1024 floats
        const int lm = ttid >> 2, kq = (ttid & 3) * 4;
        const int bk = ttid >> 4, bn = (ttid & 15) * 4;
        const int ty = ttid >> 4, tx = ttid & 15;
        const int barid = team + 1;

        for (int rt = 0; rt < 2; rt++) {
            const int row0 = b * 256 + (team * 2 + rt) * 64;
            const float mval = mask[row0 + lm];
            for (int ct = 0; ct < 8; ct++) {
                const int n0 = ct * 64;
                float acc[4][4];
#pragma unroll
                for (int i = 0; i < 4; i++)
#pragma unroll
                    for (int j = 0; j < 4; j++) acc[i][j] = 0.f;

                for (int kt = 0; kt < DD / 16; kt++) {
                    float4 a = *(const float4*)&seq[(size_t)(row0 + lm) * DD + kt * 16 + kq];
                    As[(kq + 0) * 64 + lm] = a.x * mval;
                    As[(kq + 1) * 64 + lm] = a.y * mval;
                    As[(kq + 2) * 64 + lm] = a.z * mval;
                    As[(kq + 3) * 64 + lm] = a.w * mval;
                    *(float4*)&Bs[bk * 64 + bn] =
                        *(const float4*)&Wi[(size_t)(kt * 16 + bk) * DD + n0 + bn];
                    asm volatile("bar.sync %0, 256;" :: "r"(barid) : "memory");
#pragma unroll
                    for (int k = 0; k < 16; k++) {
                        float4 av = *(const float4*)&As[k * 64 + ty * 4];
                        float4 bv = *(const float4*)&Bs[k * 64 + tx * 4];
                        float am[4] = {av.x, av.y, av.z, av.w};
                        float bb[4] = {bv.x, bv.y, bv.z, bv.w};
#pragma unroll
                        for (int i = 0; i < 4; i++)
#pragma unroll
                            for (int j = 0; j < 4; j++) acc[i][j] += am[i] * bb[j];
                    }
                    asm volatile("bar.sync %0, 256;" :: "r"(barid) : "memory");
                }
#pragma unroll
                for (int i = 0; i < 4; i++)
#pragma unroll
                    for (int j = 0; j < 4; j++) {
                        int n = n0 + tx * 4 + j;
                        g_X[(size_t)(row0 + ty * 4 + i) * DD + n] = acc[i][j] + bi[n];
                    }
            }
        }
        __syncthreads();
    }

    // =============== prologue 2: warp-parallel LN of the same 256 rows ===============
    {
        const float4 g0 = *(const float4*)(lng + lane * 16);
        const float4 g1 = *(const float4*)(lng + lane * 16 + 4);
        const float4 g2 = *(const float4*)(lng + lane * 16 + 8);
        const float4 g3 = *(const float4*)(lng + lane * 16 + 12);
        const float4 h0 = *(const float4*)(lnb + lane * 16);
        const float4 h1 = *(const float4*)(lnb + lane * 16 + 4);
        const float4 h2 = *(const float4*)(lnb + lane * 16 + 8);
        const float4 h3 = *(const float4*)(lnb + lane * 16 + 12);

        for (int r = 0; r < 16; r++) {
            const int row = b * 256 + warp * 16 + r;
            float* xp = g_X + (size_t)row * DD + lane * 16;
            float4 v0 = *(float4*)(xp);
            float4 v1 = *(float4*)(xp + 4);
            float4 v2 = *(float4*)(xp + 8);
            float4 v3 = *(float4*)(xp + 12);

            float s = v0.x + v0.y + v0.z + v0.w + v1.x + v1.y + v1.z + v1.w
                    + v2.x + v2.y + v2.z + v2.w + v3.x + v3.y + v3.z + v3.w;
#pragma unroll
            for (int o = 16; o; o >>= 1) s += __shfl_xor_sync(0xffffffffu, s, o);
            float mean = s * (1.f / DD);

            float q =
                (v0.x-mean)*(v0.x-mean) + (v0.y-mean)*(v0.y-mean) +
                (v0.z-mean)*(v0.z-mean) + (v0.w-mean)*(v0.w-mean) +
                (v1.x-mean)*(v1.x-mean) + (v1.y-mean)*(v1.y-mean) +
                (v1.z-mean)*(v1.z-mean) + (v1.w-mean)*(v1.w-mean) +
                (v2.x-mean)*(v2.x-mean) + (v2.y-mean)*(v2.y-mean) +
                (v2.z-mean)*(v2.z-mean) + (v2.w-mean)*(v2.w-mean) +
                (v3.x-mean)*(v3.x-mean) + (v3.y-mean)*(v3.y-mean) +
                (v3.z-mean)*(v3.z-mean) + (v3.w-mean)*(v3.w-mean);
#pragma unroll
            for (int o = 16; o; o >>= 1) q += __shfl_xor_sync(0xffffffffu, q, o);
            float rs = rsqrtf(q * (1.f / DD) + 1e-5f);

            float mval = mask[row];
            v0.x = ((v0.x-mean)*rs*g0.x + h0.x)*mval; v0.y = ((v0.y-mean)*rs*g0.y + h0.y)*mval;
            v0.z = ((v0.z-mean)*rs*g0.z + h0.z)*mval; v0.w = ((v0.w-mean)*rs*g0.w + h0.w)*mval;
            v1.x = ((v1.x-mean)*rs*g1.x + h1.x)*mval; v1.y = ((v1.y-mean)*rs*g1.y + h1.y)*mval;
            v1.z = ((v1.z-mean)*rs*g1.z + h1.z)*mval; v1.w = ((v1.w-mean)*rs*g1.w + h1.w)*mval;
            v2.x = ((v2.x-mean)*rs*g2.x + h2.x)*mval; v2.y = ((v2.y-mean)*rs*g2.y + h2.y)*mval;
            v2.z = ((v2.z-mean)*rs*g2.z + h2.z)*mval; v2.w = ((v2.w-mean)*rs*g2.w + h2.w)*mval;
            v3.x = ((v3.x-mean)*rs*g3.x + h3.x)*mval; v3.y = ((v3.y-mean)*rs*g3.y + h3.y)*mval;
            v3.z = ((v3.z-mean)*rs*g3.z + h3.z)*mval; v3.w = ((v3.w-mean)*rs*g3.w + h3.w)*mval;
            *(float4*)(xp)      = v0;
            *(float4*)(xp + 4)  = v1;
            *(float4*)(xp + 8)  = v2;
            *(float4*)(xp + 12) = v3;
        }
    }

    // init carry (ht and gs held in registers for block b; g_ht mirrored for other blocks)
    float hr = 0.f, gsr = 0.f;
    float lngv = 0.f, lnbv = 0.f;
    if (b < NN) {
        float s = START[tid];
        g_ht[b * DD + tid] = s;
        hr = s; gsr = s;
        lngv = lng[tid]; lnbv = lnb[tid];
    }
    gbar(&barc);   // all stripes of g_X + carries visible; smem tiles free for staging

    // =============== scan ===============
    const int mg = lane & 15;
    const int ng = lane >> 4;
    const int k0 = warp * 64;                 // 16-way k-split
    float* const Abuf = (float*)smch + warp * PWS;   // staging + partials
    const float b1v = b1[nA0 + (tid & 7)];
    const float b2v0 = b2[nB0 + (tid & 15)];
    const float b2v1 = b2[nB0 + ((tid + 512) & 15)];
    const int mr0 = 2 * mg, mr1 = 2 * mg + 1, mr2 = 2 * mg + 32, mr3 = 2 * mg + 33;

    for (int t = 0; t < SS; t++) {
        // ---------- phase A: inter = gelu(cat @ W1 + b1); block owns 8 cols ----------
        {
            ull acc[4][2];
#pragma unroll
            for (int i = 0; i < 4; i++) { acc[i][0] = 0; acc[i][1] = 0; }

            const float *base0, *base1;
            if (warp < 8) {
                base0 = g_ht + (size_t)lane * DD + k0;
                base1 = g_ht + (size_t)(lane + 32) * DD + k0;
            } else {
                size_t off = (size_t)t * DD + (k0 - 512);
                base0 = g_X + (size_t)lane * SS * DD + off;
                base1 = g_X + (size_t)(lane + 32) * SS * DD + off;
            }
            float4 c0 = ldcg4(base0), c1 = ldcg4(base0 + 4);
            float4 c2 = ldcg4(base1), c3 = ldcg4(base1 + 4);

            for (int kc = 0; kc < 8; kc++) {
                float* sb = Abuf + ((kc & 1) << 9);
                sb[0*64+lane] = c0.x; sb[1*64+lane] = c0.y;
                sb[2*64+lane] = c0.z; sb[3*64+lane] = c0.w;
                sb[4*64+lane] = c1.x; sb[5*64+lane] = c1.y;
                sb[6*64+lane] = c1.z; sb[7*64+lane] = c1.w;
                sb[0*64+lane+32] = c2.x; sb[1*64+lane+32] = c2.y;
                sb[2*64+lane+32] = c2.z; sb[3*64+lane+32] = c2.w;
                sb[4*64+lane+32] = c3.x; sb[5*64+lane+32] = c3.y;
                sb[6*64+lane+32] = c3.z; sb[7*64+lane+32] = c3.w;
                if (kc < 7) {
                    const float* q0 = base0 + (kc + 1) * 8;
                    const float* q1 = base1 + (kc + 1) * 8;
                    c0 = ldcg4(q0); c1 = ldcg4(q0 + 4);
                    c2 = ldcg4(q1); c3 = ldcg4(q1 + 4);
                }
                __syncwarp();
                const float* wk = sW1 + (size_t)(k0 + kc * 8) * 8 + ng * 4;
#pragma unroll
                for (int kk = 0; kk < 8; kk++) {
                    float2 alo = *(const float2*)(sb + kk * 64 + 2 * mg);
                    float2 ahi = *(const float2*)(sb + kk * 64 + 32 + 2 * mg);
                    ull a0 = dup2(alo.x), a1 = dup2(alo.y);
                    ull a2 = dup2(ahi.x), a3 = dup2(ahi.y);
                    ulonglong2 w = *(const ulonglong2*)(wk + kk * 8);
                    fma2(acc[0][0], a0, w.x); fma2(acc[0][1], a0, w.y);
                    fma2(acc[1][0], a1, w.x); fma2(acc[1][1], a1, w.y);
                    fma2(acc[2][0], a2, w.x); fma2(acc[2][1], a2, w.y);
                    fma2(acc[3][0], a3, w.x); fma2(acc[3][1], a3, w.y);
                }
            }
            __syncwarp();
            // partials: layout [n][68], n = ng*4 + 2p (+1), m = mr
            {
                const int mr[4] = {mr0, mr1, mr2, mr3};
#pragma unroll
                for (int mi = 0; mi < 4; mi++)
#pragma unroll
                    for (int p = 0; p < 2; p++) {
                        float2 f = unp(acc[mi][p]);
                        int n = ng * 4 + 2 * p;
                        Abuf[n * 68 + mr[mi]] = f.x;
                        Abuf[(n + 1) * 68 + mr[mi]] = f.y;
                    }
            }
            __syncthreads();
            {
                int nl = tid & 7, m = tid >> 3;
                float s = b1v;
#pragma unroll
                for (int w = 0; w < 16; w++) s += Rall[w * PWS + nl * 68 + m];
                __stcg(&g_inter[m * CC + nA0 + nl], gelu_t(s));
            }
        }
        gbar(&barc);

        // ---------- phase B: cont = inter @ W2 + b2; block owns 16 cols ----------
        {
            ull acc[4][4];
#pragma unroll
            for (int i = 0; i < 4; i++)
#pragma unroll
                for (int j = 0; j < 4; j++) acc[i][j] = 0;

            const float* base0 = g_inter + (size_t)lane * CC + k0;
            const float* base1 = g_inter + (size_t)(lane + 32) * CC + k0;
            float4 c0 = ldcg4(base0), c1 = ldcg4(base0 + 4);
            float4 c2 = ldcg4(base1), c3 = ldcg4(base1 + 4);

            for (int kc = 0; kc < 8; kc++) {
                float* sb = Abuf + ((kc & 1) << 9);
                sb[0*64+lane] = c0.x; sb[1*64+lane] = c0.y;
                sb[2*64+lane] = c0.z; sb[3*64+lane] = c0.w;
                sb[4*64+lane] = c1.x; sb[5*64+lane] = c1.y;
                sb[6*64+lane] = c1.z; sb[7*64+lane] = c1.w;
                sb[0*64+lane+32] = c2.x; sb[1*64+lane+32] = c2.y;
                sb[2*64+lane+32] = c2.z; sb[3*64+lane+32] = c2.w;
                sb[4*64+lane+32] = c3.x; sb[5*64+lane+32] = c3.y;
                sb[6*64+lane+32] = c3.z; sb[7*64+lane+32] = c3.w;
                if (kc < 7) {
                    const float* q0 = base0 + (kc + 1) * 8;
                    const float* q1 = base1 + (kc + 1) * 8;
                    c0 = ldcg4(q0); c1 = ldcg4(q0 + 4);
                    c2 = ldcg4(q1); c3 = ldcg4(q1 + 4);
                }
                __syncwarp();
                const float* wk = sW2 + (size_t)(k0 + kc * 8) * 16 + ng * 8;
#pragma unroll
                for (int kk = 0; kk < 8; kk++) {
                    float2 alo = *(const float2*)(sb + kk * 64 + 2 * mg);
                    float2 ahi = *(const float2*)(sb + kk * 64 + 32 + 2 * mg);
                    ull a0 = dup2(alo.x), a1 = dup2(alo.y);
                    ull a2 = dup2(ahi.x), a3 = dup2(ahi.y);
                    const float* wr = wk + kk * 16;
                    ulonglong2 w0 = *(const ulonglong2*)(wr);
                    ulonglong2 w1 = *(const ulonglong2*)(wr + 4);
                    fma2(acc[0][0], a0, w0.x); fma2(acc[0][1], a0, w0.y);
                    fma2(acc[0][2], a0, w1.x); fma2(acc[0][3], a0, w1.y);
                    fma2(acc[1][0], a1, w0.x); fma2(acc[1][1], a1, w0.y);
                    fma2(acc[1][2], a1, w1.x); fma2(acc[1][3], a1, w1.y);
                    fma2(acc[2][0], a2, w0.x); fma2(acc[2][1], a2, w0.y);
                    fma2(acc[2][2], a2, w1.x); fma2(acc[2][3], a2, w1.y);
                    fma2(acc[3][0], a3, w0.x); fma2(acc[3][1], a3, w0.y);
                    fma2(acc[3][2], a3, w1.x); fma2(acc[3][3], a3, w1.y);
                }
            }
            __syncwarp();
            {
                const int mr[4] = {mr0, mr1, mr2, mr3};
#pragma unroll
                for (int mi = 0; mi < 4; mi++)
#pragma unroll
                    for (int np = 0; np < 4; np++) {
                        float2 f = unp(acc[mi][np]);
                        int n = ng * 8 + np * 2;
                        Abuf[n * 68 + mr[mi]] = f.x;
                        Abuf[(n + 1) * 68 + mr[mi]] = f.y;
                    }
            }
            __syncthreads();
#pragma unroll
            for (int j = 0; j < 2; j++) {
                int idx = tid + 512 * j;
                int nl = idx & 15, m = idx >> 4;
                float s = (j == 0) ? b2v0 : b2v1;
#pragma unroll
                for (int w = 0; w < 16; w++) s += Rall[w * PWS + nl * 68 + m];
                __stcg(&g_cont[m * (4 * DD) + nB0 + nl], s);
            }
        }
        gbar(&barc);

        // ---------- phase C: gates + LN + state update (blocks 0..63) ----------
        if (b < NN) {
            float mval = mask[(size_t)b * SS + t];
            const float* cb = g_cont + b * (4 * DD);
            float c0 = __ldcg(cb + tid);
            float c1 = __ldcg(cb + 512 + tid);
            float c2 = __ldcg(cb + 1024 + tid);
            float c3 = __ldcg(cb + 1536 + tid);
            float x0 = g_X[((size_t)b * SS + t) * DD + tid];
            float v = sigm(c0) * hr + sigm(c1) * x0 + sigm(c2) * c3;
            float mean = bsum512(v, scC) * (1.f / DD);
            float e = v - mean;
            float var = bsum512(e * e, scC) * (1.f / DD);
            float rs = rsqrtf(var + 1e-5f);
            float hn = e * rs * lngv + lnbv;
            hr = hn;
            g_ht[b * DD + tid] = hn;
            out[((size_t)b * SS + t) * DD + tid] = hn * mval;
            gsr = mval * hn + (1.f - mval) * gsr;
        }
        gbar(&barc);
    }

    // final global_state
    if (b < NN) {
        out[(size_t)NN * SS * DD + b * DD + tid] = gsr;
    }
}

extern "C" void kernel_launch(void* const* d_in, const int* in_sizes, int n_in,
                              void* d_out, int out_size) {
    (void)in_sizes; (void)n_in; (void)out_size;
    const float* seq   = (const float*)d_in[0];
    const float* mask  = (const float*)d_in[1];
    const float* START = (const float*)d_in[2];
    const float* Wi    = (const float*)d_in[3];
    const float* bi    = (const float*)d_in[4];
    const float* W1    = (const float*)d_in[5];
    const float* b1    = (const float*)d_in[6];
    const float* W2    = (const float*)d_in[7];
    const float* b2    = (const float*)d_in[8];
    const float* lng   = (const float*)d_in[9];
    const float* lnb   = (const float*)d_in[10];
    float* out = (float*)d_out;

    static bool attr_done = false;
    if (!attr_done) {
        cudaFuncSetAttribute(k_main, cudaFuncAttributeMaxDynamicSharedMemorySize,
                             SMEM_MAIN);
        attr_done = true;
    }

    k_reset<<<1, 1>>>();
    k_main<<<GRID, NTHREADS, SMEM_MAIN>>>(seq, mask, START, Wi, bi,
                                          W1, b1, W2, b2, lng, lnb, out);
}